// round 2
// baseline (speedup 1.0000x reference)
#include <cuda_runtime.h>

// TransH-style scoring:
//   v = bases[pos_r]                        (used for BOTH pos and neg sides)
//   s_pos = ent[pos_h] + vvrel[pos_r] - ent[pos_t]
//   s_neg = ent[neg_h] + vvrel[neg_r] - ent[neg_t]
//   proj(x) = x - (v.x)/(v.v) * v           (linear => project the SUM once)
//   pos = sum|proj(s_pos)| ; neg = sum|proj(s_neg)|
//
// D = 128 floats = 32 float4 => one warp per row, one float4 per lane.

#define D4 32  // 128 floats / 4

__global__ __launch_bounds__(256, 8)
void transh_kernel(const int* __restrict__ pos_h,
                   const int* __restrict__ pos_t,
                   const int* __restrict__ pos_r,
                   const int* __restrict__ neg_h,
                   const int* __restrict__ neg_t,
                   const int* __restrict__ neg_r,
                   const float4* __restrict__ ent,
                   const float4* __restrict__ vvrel,
                   const float4* __restrict__ bases,
                   float* __restrict__ out,
                   int n)
{
    const int warp = (blockIdx.x * blockDim.x + threadIdx.x) >> 5;
    const int lane = threadIdx.x & 31;
    if (warp >= n) return;

    // Uniform index loads (all lanes same address -> L1 broadcast)
    const int ih = pos_h[warp];
    const int it = pos_t[warp];
    const int ir = pos_r[warp];
    const int jh = neg_h[warp];
    const int jt = neg_t[warp];
    const int jr = neg_r[warp];

    // Gather: each lane one float4, warp covers the full 512B row.
    const float4 v  = __ldg(&bases[(size_t)ir * D4 + lane]);
    const float4 ph = __ldg(&ent  [(size_t)ih * D4 + lane]);
    const float4 pt = __ldg(&ent  [(size_t)it * D4 + lane]);
    const float4 pr = __ldg(&vvrel[(size_t)ir * D4 + lane]);
    const float4 nh = __ldg(&ent  [(size_t)jh * D4 + lane]);
    const float4 nt = __ldg(&ent  [(size_t)jt * D4 + lane]);
    const float4 nr = __ldg(&vvrel[(size_t)jr * D4 + lane]);

    // s = h + r - t (projection is linear, so sum first)
    float4 sp, sn;
    sp.x = ph.x + pr.x - pt.x;  sp.y = ph.y + pr.y - pt.y;
    sp.z = ph.z + pr.z - pt.z;  sp.w = ph.w + pr.w - pt.w;
    sn.x = nh.x + nr.x - nt.x;  sn.y = nh.y + nr.y - nt.y;
    sn.z = nh.z + nr.z - nt.z;  sn.w = nh.w + nr.w - nt.w;

    // Three partial dots per lane
    float dvv = v.x*v.x + v.y*v.y + v.z*v.z + v.w*v.w;
    float dvp = v.x*sp.x + v.y*sp.y + v.z*sp.z + v.w*sp.w;
    float dvn = v.x*sn.x + v.y*sn.y + v.z*sn.z + v.w*sn.w;

    // Butterfly reduce -> every lane holds the full dots
    #pragma unroll
    for (int o = 16; o > 0; o >>= 1) {
        dvv += __shfl_xor_sync(0xFFFFFFFFu, dvv, o);
        dvp += __shfl_xor_sync(0xFFFFFFFFu, dvp, o);
        dvn += __shfl_xor_sync(0xFFFFFFFFu, dvn, o);
    }

    const float inv = 1.0f / dvv;
    const float cp = dvp * inv;
    const float cn = dvn * inv;

    float ap = fabsf(sp.x - cp * v.x) + fabsf(sp.y - cp * v.y)
             + fabsf(sp.z - cp * v.z) + fabsf(sp.w - cp * v.w);
    float an = fabsf(sn.x - cn * v.x) + fabsf(sn.y - cn * v.y)
             + fabsf(sn.z - cn * v.z) + fabsf(sn.w - cn * v.w);

    #pragma unroll
    for (int o = 16; o > 0; o >>= 1) {
        ap += __shfl_xor_sync(0xFFFFFFFFu, ap, o);
        an += __shfl_xor_sync(0xFFFFFFFFu, an, o);
    }

    if (lane == 0) {
        out[warp]     = ap;   // pos
        out[n + warp] = an;   // neg
    }
}

extern "C" void kernel_launch(void* const* d_in, const int* in_sizes, int n_in,
                              void* d_out, int out_size)
{
    const int*    pos_h = (const int*)d_in[0];
    const int*    pos_t = (const int*)d_in[1];
    const int*    pos_r = (const int*)d_in[2];
    const int*    neg_h = (const int*)d_in[3];
    const int*    neg_t = (const int*)d_in[4];
    const int*    neg_r = (const int*)d_in[5];
    const float4* ent   = (const float4*)d_in[6];
    const float4* vvrel = (const float4*)d_in[7];
    const float4* bases = (const float4*)d_in[8];
    float*        out   = (float*)d_out;

    const int n = in_sizes[0];            // 65536 rows
    const int warps_per_block = 256 / 32; // 8
    const int blocks = (n + warps_per_block - 1) / warps_per_block;

    transh_kernel<<<blocks, 256>>>(pos_h, pos_t, pos_r,
                                   neg_h, neg_t, neg_r,
                                   ent, vvrel, bases, out, n);
}

// round 3
// speedup vs baseline: 1.0882x; 1.0882x over previous
#include <cuda_runtime.h>

// TransH scoring, 2 rows per warp for doubled memory-level parallelism.
// Projection is linear: proj(h)+proj(r)-proj(t) = proj(h+r-t).
// D = 128 floats = 32 float4 -> one float4 per lane per row.

#define D4 32
#define ROWS_PER_WARP 2

__global__ __launch_bounds__(256)
void transh_kernel(const int* __restrict__ pos_h,
                   const int* __restrict__ pos_t,
                   const int* __restrict__ pos_r,
                   const int* __restrict__ neg_h,
                   const int* __restrict__ neg_t,
                   const int* __restrict__ neg_r,
                   const float4* __restrict__ ent,
                   const float4* __restrict__ vvrel,
                   const float4* __restrict__ bases,
                   float* __restrict__ out,
                   int n)
{
    const int warp = (blockIdx.x * blockDim.x + threadIdx.x) >> 5;
    const int lane = threadIdx.x & 31;
    const int row0 = warp * ROWS_PER_WARP;
    if (row0 >= n) return;

    // ---- indices for both rows (uniform per warp -> broadcast) ----
    const int r1 = row0 + 1;  // n is a multiple of 2 in this problem (65536)

    const int ih0 = pos_h[row0], it0 = pos_t[row0], ir0 = pos_r[row0];
    const int jh0 = neg_h[row0], jt0 = neg_t[row0], jr0 = neg_r[row0];
    const int ih1 = pos_h[r1],   it1 = pos_t[r1],   ir1 = pos_r[r1];
    const int jh1 = neg_h[r1],   jt1 = neg_t[r1],   jr1 = neg_r[r1];

    // ---- front-batch all 14 gathers (max MLP) ----
    const float4 v0  = __ldg(&bases[(size_t)ir0 * D4 + lane]);
    const float4 ph0 = __ldg(&ent  [(size_t)ih0 * D4 + lane]);
    const float4 pt0 = __ldg(&ent  [(size_t)it0 * D4 + lane]);
    const float4 pr0 = __ldg(&vvrel[(size_t)ir0 * D4 + lane]);
    const float4 nh0 = __ldg(&ent  [(size_t)jh0 * D4 + lane]);
    const float4 nt0 = __ldg(&ent  [(size_t)jt0 * D4 + lane]);
    const float4 nr0 = __ldg(&vvrel[(size_t)jr0 * D4 + lane]);

    const float4 v1  = __ldg(&bases[(size_t)ir1 * D4 + lane]);
    const float4 ph1 = __ldg(&ent  [(size_t)ih1 * D4 + lane]);
    const float4 pt1 = __ldg(&ent  [(size_t)it1 * D4 + lane]);
    const float4 pr1 = __ldg(&vvrel[(size_t)ir1 * D4 + lane]);
    const float4 nh1 = __ldg(&ent  [(size_t)jh1 * D4 + lane]);
    const float4 nt1 = __ldg(&ent  [(size_t)jt1 * D4 + lane]);
    const float4 nr1 = __ldg(&vvrel[(size_t)jr1 * D4 + lane]);

    // ---- row 0 ----
    float4 sp0, sn0;
    sp0.x = ph0.x + pr0.x - pt0.x;  sp0.y = ph0.y + pr0.y - pt0.y;
    sp0.z = ph0.z + pr0.z - pt0.z;  sp0.w = ph0.w + pr0.w - pt0.w;
    sn0.x = nh0.x + nr0.x - nt0.x;  sn0.y = nh0.y + nr0.y - nt0.y;
    sn0.z = nh0.z + nr0.z - nt0.z;  sn0.w = nh0.w + nr0.w - nt0.w;

    // ---- row 1 ----
    float4 sp1, sn1;
    sp1.x = ph1.x + pr1.x - pt1.x;  sp1.y = ph1.y + pr1.y - pt1.y;
    sp1.z = ph1.z + pr1.z - pt1.z;  sp1.w = ph1.w + pr1.w - pt1.w;
    sn1.x = nh1.x + nr1.x - nt1.x;  sn1.y = nh1.y + nr1.y - nt1.y;
    sn1.z = nh1.z + nr1.z - nt1.z;  sn1.w = nh1.w + nr1.w - nt1.w;

    // ---- six dots, one fused butterfly ----
    float dvv0 = v0.x*v0.x + v0.y*v0.y + v0.z*v0.z + v0.w*v0.w;
    float dvp0 = v0.x*sp0.x + v0.y*sp0.y + v0.z*sp0.z + v0.w*sp0.w;
    float dvn0 = v0.x*sn0.x + v0.y*sn0.y + v0.z*sn0.z + v0.w*sn0.w;
    float dvv1 = v1.x*v1.x + v1.y*v1.y + v1.z*v1.z + v1.w*v1.w;
    float dvp1 = v1.x*sp1.x + v1.y*sp1.y + v1.z*sp1.z + v1.w*sp1.w;
    float dvn1 = v1.x*sn1.x + v1.y*sn1.y + v1.z*sn1.z + v1.w*sn1.w;

    #pragma unroll
    for (int o = 16; o > 0; o >>= 1) {
        dvv0 += __shfl_xor_sync(0xFFFFFFFFu, dvv0, o);
        dvp0 += __shfl_xor_sync(0xFFFFFFFFu, dvp0, o);
        dvn0 += __shfl_xor_sync(0xFFFFFFFFu, dvn0, o);
        dvv1 += __shfl_xor_sync(0xFFFFFFFFu, dvv1, o);
        dvp1 += __shfl_xor_sync(0xFFFFFFFFu, dvp1, o);
        dvn1 += __shfl_xor_sync(0xFFFFFFFFu, dvn1, o);
    }

    const float inv0 = 1.0f / dvv0;
    const float cp0 = dvp0 * inv0, cn0 = dvn0 * inv0;
    const float inv1 = 1.0f / dvv1;
    const float cp1 = dvp1 * inv1, cn1 = dvn1 * inv1;

    float ap0 = fabsf(sp0.x - cp0*v0.x) + fabsf(sp0.y - cp0*v0.y)
              + fabsf(sp0.z - cp0*v0.z) + fabsf(sp0.w - cp0*v0.w);
    float an0 = fabsf(sn0.x - cn0*v0.x) + fabsf(sn0.y - cn0*v0.y)
              + fabsf(sn0.z - cn0*v0.z) + fabsf(sn0.w - cn0*v0.w);
    float ap1 = fabsf(sp1.x - cp1*v1.x) + fabsf(sp1.y - cp1*v1.y)
              + fabsf(sp1.z - cp1*v1.z) + fabsf(sp1.w - cp1*v1.w);
    float an1 = fabsf(sn1.x - cn1*v1.x) + fabsf(sn1.y - cn1*v1.y)
              + fabsf(sn1.z - cn1*v1.z) + fabsf(sn1.w - cn1*v1.w);

    #pragma unroll
    for (int o = 16; o > 0; o >>= 1) {
        ap0 += __shfl_xor_sync(0xFFFFFFFFu, ap0, o);
        an0 += __shfl_xor_sync(0xFFFFFFFFu, an0, o);
        ap1 += __shfl_xor_sync(0xFFFFFFFFu, ap1, o);
        an1 += __shfl_xor_sync(0xFFFFFFFFu, an1, o);
    }

    if (lane == 0) {
        out[row0]     = ap0;
        out[r1]       = ap1;
        out[n + row0] = an0;
        out[n + r1]   = an1;
    }
}

extern "C" void kernel_launch(void* const* d_in, const int* in_sizes, int n_in,
                              void* d_out, int out_size)
{
    const int*    pos_h = (const int*)d_in[0];
    const int*    pos_t = (const int*)d_in[1];
    const int*    pos_r = (const int*)d_in[2];
    const int*    neg_h = (const int*)d_in[3];
    const int*    neg_t = (const int*)d_in[4];
    const int*    neg_r = (const int*)d_in[5];
    const float4* ent   = (const float4*)d_in[6];
    const float4* vvrel = (const float4*)d_in[7];
    const float4* bases = (const float4*)d_in[8];
    float*        out   = (float*)d_out;

    const int n = in_sizes[0];                      // 65536 rows
    const int rows_per_block = (256 / 32) * ROWS_PER_WARP;  // 16
    const int blocks = (n + rows_per_block - 1) / rows_per_block;

    transh_kernel<<<blocks, 256>>>(pos_h, pos_t, pos_r,
                                   neg_h, neg_t, neg_r,
                                   ent, vvrel, bases, out, n);
}